// round 4
// baseline (speedup 1.0000x reference)
#include <cuda_runtime.h>

// NAF layer: A = -0.5 * d^T (L L^T) d  ==  -0.5 * ||L^T d||^2
// L is lower-triangular, packed row-major in L_flat (tril_indices order):
//   element (i,j), i>=j, lives at flat index i*(i+1)/2 + j.
// Diagonal entries are exp(x)+eps; off-diagonal raw.
//
// One warp per batch row. Lane l owns output columns j=l and j=l+32.
// Loop over triangle rows i; d[i] broadcast by shuffle; loads are contiguous
// within the warp (triangle row segments are contiguous & abutting), so every
// L_flat byte is fetched exactly once, fully coalesced -> HBM-streaming bound.

#define NB_ACTIONS 64
#define NB_ELEMS   2080
#define EPSV       1e-7f

__global__ __launch_bounds__(256, 8)
void naf_kernel(const float* __restrict__ Lf,
                const float* __restrict__ mu,
                const float* __restrict__ a,
                float* __restrict__ out,
                int B)
{
    const int warp = (blockIdx.x * blockDim.x + threadIdx.x) >> 5;
    const int lane = threadIdx.x & 31;
    if (warp >= B) return;

    const float* __restrict__ Lrow = Lf + (size_t)warp * NB_ELEMS;
    const size_t vb = (size_t)warp * NB_ACTIONS;

    // d = a - mu, lane l holds d[l] (lo) and d[l+32] (hi)
    const float dlo = a[vb + lane]      - mu[vb + lane];
    const float dhi = a[vb + 32 + lane] - mu[vb + 32 + lane];

    float y0 = 0.0f;   // accumulator for column j = lane
    float y1 = 0.0f;   // accumulator for column j = lane + 32

    int tri = 0;       // i*(i+1)/2 at loop head

    // Triangle rows i = 0..31: only columns j<=i<=31 exist -> y0 only.
    #pragma unroll
    for (int i = 0; i < 32; ++i) {
        const float di = __shfl_sync(0xffffffffu, dlo, i);
        if (lane <= i) {
            float v = Lrow[tri + lane];
            if (lane == i) v = expf(v) + EPSV;   // diagonal
            y0 = fmaf(v, di, y0);
        }
        tri += i + 1;
    }

    // Triangle rows i = 32..63: first 32 columns always present (all y0),
    // columns 32..i go to y1. Diagonal (j=i) is in the hi chunk.
    #pragma unroll
    for (int i = 32; i < 64; ++i) {
        const float di = __shfl_sync(0xffffffffu, dhi, i - 32);
        {
            const float v = Lrow[tri + lane];        // j = lane <= 31 < i, never diag
            y0 = fmaf(v, di, y0);
        }
        if (lane + 32 <= i) {
            float v = Lrow[tri + 32 + lane];         // j = lane + 32
            if (lane + 32 == i) v = expf(v) + EPSV;  // diagonal
            y1 = fmaf(v, di, y1);
        }
        tri += i + 1;
    }

    // quad = sum_j y_j^2 ; butterfly warp reduction
    float q = fmaf(y0, y0, y1 * y1);
    #pragma unroll
    for (int off = 16; off; off >>= 1)
        q += __shfl_xor_sync(0xffffffffu, q, off);

    if (lane == 0) out[warp] = -0.5f * q;
}

extern "C" void kernel_launch(void* const* d_in, const int* in_sizes, int n_in,
                              void* d_out, int out_size)
{
    const float* Lf = (const float*)d_in[0];   // [B, 2080]
    const float* mu = (const float*)d_in[1];   // [B, 64]
    const float* a  = (const float*)d_in[2];   // [B, 64]
    float* out = (float*)d_out;                // [B, 1]

    const int B = in_sizes[0] / NB_ELEMS;

    const int threads = 256;                   // 8 warps = 8 rows per block
    const int rows_per_block = threads / 32;
    const int blocks = (B + rows_per_block - 1) / rows_per_block;

    naf_kernel<<<blocks, threads>>>(Lf, mu, a, out, B);
}

// round 6
// speedup vs baseline: 1.7864x; 1.7864x over previous
#include <cuda_runtime.h>

// NAF layer: A = -0.5 * d^T (L L^T) d  ==  -0.5 * ||L^T d||^2
// L lower-triangular, packed row-major (tril order): (i,j) at i*(i+1)/2 + j.
// Diagonal entries exp(x)+eps, off-diagonal raw.
//
// One warp per batch row; lane l owns columns j=l and j=l+32.
// R4 lesson: branchy predicated loads killed MLP (regs=21, DRAM 23%).
// This version issues ALL loads unconditionally in batches of 8 before any
// consuming FMA (every speculative address stays inside the row's 2080
// floats), and predicates arithmetically via a select on the multiplier.

#define NB_ACTIONS 64
#define NB_ELEMS   2080
#define EPSV       1e-7f
#define TRI(i) ((i) * ((i) + 1) / 2)

__global__ __launch_bounds__(256, 4)
void naf_kernel(const float* __restrict__ Lf,
                const float* __restrict__ mu,
                const float* __restrict__ a,
                float* __restrict__ out,
                int B)
{
    const int warp = (blockIdx.x * blockDim.x + threadIdx.x) >> 5;
    const int lane = threadIdx.x & 31;
    if (warp >= B) return;

    const float* __restrict__ Lrow = Lf + (size_t)warp * NB_ELEMS;
    const size_t vb = (size_t)warp * NB_ACTIONS;

    // d = a - mu; lane l holds d[l] (lo) and d[l+32] (hi)
    const float dlo = a[vb + lane]      - mu[vb + lane];
    const float dhi = a[vb + 32 + lane] - mu[vb + 32 + lane];

    float y0 = 0.0f;   // column j = lane
    float y1 = 0.0f;   // column j = lane + 32

    // ---- Rows 0..31: batches of 8 rows, 8 independent loads per batch ----
    #pragma unroll
    for (int i0 = 0; i0 < 32; i0 += 8) {
        float v[8];
        #pragma unroll
        for (int k = 0; k < 8; ++k) {
            const int i = i0 + k;
            v[k] = Lrow[TRI(i) + lane];          // unconditional, in-bounds
        }
        #pragma unroll
        for (int k = 0; k < 8; ++k) {
            const int i = i0 + k;
            const float di  = __shfl_sync(0xffffffffu, dlo, i);
            const float val = (lane == i) ? (expf(v[k]) + EPSV) : v[k];
            const float m   = (lane <= i) ? di : 0.0f;
            y0 = fmaf(val, m, y0);
        }
    }

    // ---- Rows 32..63: batches of 4 rows, 8 independent loads per batch ----
    // lo part (j=lane<=31<i): always valid, never diagonal.
    // hi part (j=lane+32): valid when lane+32<=i; diagonal when lane+32==i.
    #pragma unroll
    for (int i0 = 32; i0 < 64; i0 += 4) {
        float vlo[4], vhi[4];
        #pragma unroll
        for (int k = 0; k < 4; ++k) {
            const int i = i0 + k;
            vlo[k] = Lrow[TRI(i) + lane];
            vhi[k] = Lrow[TRI(i) + 32 + lane];   // unconditional, in-bounds
        }
        #pragma unroll
        for (int k = 0; k < 4; ++k) {
            const int i = i0 + k;
            const float di = __shfl_sync(0xffffffffu, dhi, i - 32);
            y0 = fmaf(vlo[k], di, y0);
            const float val = (lane + 32 == i) ? (expf(vhi[k]) + EPSV) : vhi[k];
            const float m   = (lane + 32 <= i) ? di : 0.0f;
            y1 = fmaf(val, m, y1);
        }
    }

    // quad = sum_j y_j^2 ; butterfly warp reduction
    float q = fmaf(y0, y0, y1 * y1);
    #pragma unroll
    for (int off = 16; off; off >>= 1)
        q += __shfl_xor_sync(0xffffffffu, q, off);

    if (lane == 0) out[warp] = -0.5f * q;
}

extern "C" void kernel_launch(void* const* d_in, const int* in_sizes, int n_in,
                              void* d_out, int out_size)
{
    const float* Lf = (const float*)d_in[0];   // [B, 2080]
    const float* mu = (const float*)d_in[1];   // [B, 64]
    const float* a  = (const float*)d_in[2];   // [B, 64]
    float* out = (float*)d_out;                // [B, 1]

    const int B = in_sizes[0] / NB_ELEMS;

    const int threads = 256;                   // 8 warps = 8 rows per block
    const int rows_per_block = threads / 32;
    const int blocks = (B + rows_per_block - 1) / rows_per_block;

    naf_kernel<<<blocks, threads>>>(Lf, mu, a, out, B);
}

// round 7
// speedup vs baseline: 1.9988x; 1.1189x over previous
#include <cuda_runtime.h>

// NAF layer: A = -0.5 * d^T (L L^T) d  ==  -0.5 * ||L^T d||^2
// L lower-triangular, packed row-major (tril order): (i,j) at i*(i+1)/2 + j.
// Diagonal entries exp(x)+eps, off-diagonal raw.
//
// One warp per batch row; lane l owns columns j=l and j=l+32.
// R6 lessons: (a) per-iteration expf+select cost ~64 MUFU chains/row — hoist
// the diagonal correction out of the loop (2 expf per warp total);
// (b) occ 44% capped latency hiding — target 5 blocks/SM (40 warps).
// Loads stay unconditional and batched 8-deep for MLP.

#define NB_ACTIONS 64
#define NB_ELEMS   2080
#define EPSV       1e-7f
#define TRI(i) ((i) * ((i) + 1) / 2)

__global__ __launch_bounds__(256, 5)
void naf_kernel(const float* __restrict__ Lf,
                const float* __restrict__ mu,
                const float* __restrict__ a,
                float* __restrict__ out,
                int B)
{
    const int warp = (blockIdx.x * blockDim.x + threadIdx.x) >> 5;
    const int lane = threadIdx.x & 31;
    if (warp >= B) return;

    const float* __restrict__ Lrow = Lf + (size_t)warp * NB_ELEMS;
    const size_t vb = (size_t)warp * NB_ACTIONS;

    // This lane's two diagonal elements (raw), fetched early; the lines will
    // be re-hit by the streaming loops (L2/L1 resident), cost ~2 scattered loads.
    const int j1 = lane + 32;
    const float diagRaw0 = Lrow[TRI(lane) + lane];
    const float diagRaw1 = Lrow[TRI(j1) + j1];

    // d = a - mu; lane l holds d[l] (lo) and d[l+32] (hi)
    const float dlo = a[vb + lane] - mu[vb + lane];
    const float dhi = a[vb + j1]   - mu[vb + j1];

    float y0 = 0.0f;   // column j = lane
    float y1 = 0.0f;   // column j = lane + 32

    // ---- Rows 0..31: batches of 8 rows, 8 independent loads up front ----
    // Diagonal treated as RAW here; corrected after the loops.
    #pragma unroll
    for (int i0 = 0; i0 < 32; i0 += 8) {
        float v[8];
        #pragma unroll
        for (int k = 0; k < 8; ++k)
            v[k] = Lrow[TRI(i0 + k) + lane];          // unconditional, in-bounds
        #pragma unroll
        for (int k = 0; k < 8; ++k) {
            const int i = i0 + k;
            const float di = __shfl_sync(0xffffffffu, dlo, i);
            const float m  = (lane <= i) ? di : 0.0f;
            y0 = fmaf(v[k], m, y0);
        }
    }

    // ---- Rows 32..63: batches of 4 rows, 8 independent loads up front ----
    // lo part (j=lane): always valid, never diagonal.
    // hi part (j=lane+32): masked when lane+32>i; diagonal raw, corrected later.
    #pragma unroll
    for (int i0 = 32; i0 < 64; i0 += 4) {
        float vlo[4], vhi[4];
        #pragma unroll
        for (int k = 0; k < 4; ++k) {
            const int t = TRI(i0 + k);
            vlo[k] = Lrow[t + lane];
            vhi[k] = Lrow[t + j1];                    // unconditional, in-bounds
        }
        #pragma unroll
        for (int k = 0; k < 4; ++k) {
            const int i = i0 + k;
            const float di = __shfl_sync(0xffffffffu, dhi, i - 32);
            y0 = fmaf(vlo[k], di, y0);
            const float m = (j1 <= i) ? di : 0.0f;
            y1 = fmaf(vhi[k], m, y1);
        }
    }

    // Diagonal correction: loops added raw*d_self; want (exp(raw)+eps)*d_self.
    y0 = fmaf(expf(diagRaw0) + EPSV - diagRaw0, dlo, y0);
    y1 = fmaf(expf(diagRaw1) + EPSV - diagRaw1, dhi, y1);

    // quad = sum_j y_j^2 ; butterfly warp reduction
    float q = fmaf(y0, y0, y1 * y1);
    #pragma unroll
    for (int off = 16; off; off >>= 1)
        q += __shfl_xor_sync(0xffffffffu, q, off);

    if (lane == 0) out[warp] = -0.5f * q;
}

extern "C" void kernel_launch(void* const* d_in, const int* in_sizes, int n_in,
                              void* d_out, int out_size)
{
    const float* Lf = (const float*)d_in[0];   // [B, 2080]
    const float* mu = (const float*)d_in[1];   // [B, 64]
    const float* a  = (const float*)d_in[2];   // [B, 64]
    float* out = (float*)d_out;                // [B, 1]

    const int B = in_sizes[0] / NB_ELEMS;

    const int threads = 256;                   // 8 warps = 8 rows per block
    const int rows_per_block = threads / 32;
    const int blocks = (B + rows_per_block - 1) / rows_per_block;

    naf_kernel<<<blocks, threads>>>(Lf, mu, a, out, B);
}

// round 10
// speedup vs baseline: 3.4867x; 1.7444x over previous
#include <cuda_runtime.h>
#include <cstdint>

// NAF layer: A = -0.5 * d^T (L L^T) d  ==  -0.5 * ||L^T d||^2
// L lower-triangular, packed row-major (tril order): (i,j) at i*(i+1)/2 + j.
// Diagonal entries exp(x)+eps, off-diagonal raw.
//
// R7 lesson: scalar LDG batches still exposed ~12 long-scoreboard waits per
// row (DRAM 47%). This version stages the whole 2080-float row (8320 B,
// 16B-aligned) into shared memory with 17 cp.async.cg 16B ops per warp
// (512 B per warp-instruction, no register staging), waits ONCE, then runs
// the triangle walk from conflict-free shared memory.
// One warp per batch row; lane l owns columns j=l and j=l+32.

#define NB_ACTIONS 64
#define NB_ELEMS   2080            // 520 float4 per row
#define NB_F4      520
#define EPSV       1e-7f
#define TRI(i) ((i) * ((i) + 1) / 2)
#define WPB    4                   // warps per block

__global__ __launch_bounds__(32 * WPB, 6)
void naf_kernel(const float* __restrict__ Lf,
                const float* __restrict__ mu,
                const float* __restrict__ a,
                float* __restrict__ out,
                int B)
{
    __shared__ float sbuf[WPB][NB_ELEMS];   // 33,280 B/block

    const int lane   = threadIdx.x & 31;
    const int wlocal = threadIdx.x >> 5;
    const int row    = blockIdx.x * WPB + wlocal;
    if (row >= B) return;

    float* __restrict__ sw = sbuf[wlocal];

    // ---- Stage the full row global -> shared with cp.async (MLP = 17) ----
    {
        const float4* __restrict__ src =
            (const float4*)(Lf + (size_t)row * NB_ELEMS);
        unsigned int sdst = (unsigned int)__cvta_generic_to_shared(sw);
        #pragma unroll
        for (int it = 0; it < 17; ++it) {
            const int idx = it * 32 + lane;
            if (idx < NB_F4) {
                asm volatile("cp.async.cg.shared.global [%0], [%1], 16;\n"
                             :: "r"(sdst + idx * 16), "l"(src + idx));
            }
        }
        asm volatile("cp.async.commit_group;\n");
        asm volatile("cp.async.wait_group 0;\n" ::: "memory");
        __syncwarp();
    }

    // ---- d = a - mu; lane l holds d[l] (lo) and d[l+32] (hi) ----
    const size_t vb = (size_t)row * NB_ACTIONS;
    const int j1 = lane + 32;
    const float dlo = a[vb + lane] - mu[vb + lane];
    const float dhi = a[vb + j1]   - mu[vb + j1];

    // This lane's two diagonal elements (raw) from shared
    const float diagRaw0 = sw[TRI(lane) + lane];
    const float diagRaw1 = sw[TRI(j1) + j1];

    float y0 = 0.0f;   // column j = lane
    float y1 = 0.0f;   // column j = lane + 32

    // ---- Rows 0..31: y0 only; diagonal kept raw, corrected afterwards ----
    #pragma unroll
    for (int i = 0; i < 32; ++i) {
        const float v  = sw[TRI(i) + lane];           // conflict-free LDS
        const float di = __shfl_sync(0xffffffffu, dlo, i);
        const float m  = (lane <= i) ? di : 0.0f;
        y0 = fmaf(v, m, y0);
    }

    // ---- Rows 32..63: lo part always valid; hi part masked ----
    #pragma unroll
    for (int i = 32; i < 64; ++i) {
        const int t = TRI(i);
        const float vlo = sw[t + lane];
        const float vhi = sw[t + j1];
        const float di  = __shfl_sync(0xffffffffu, dhi, i - 32);
        y0 = fmaf(vlo, di, y0);
        const float m = (j1 <= i) ? di : 0.0f;
        y1 = fmaf(vhi, m, y1);
    }

    // Diagonal correction: loops added raw*d_self; want (exp(raw)+eps)*d_self.
    y0 = fmaf(expf(diagRaw0) + EPSV - diagRaw0, dlo, y0);
    y1 = fmaf(expf(diagRaw1) + EPSV - diagRaw1, dhi, y1);

    // quad = sum_j y_j^2 ; butterfly warp reduction
    float q = fmaf(y0, y0, y1 * y1);
    #pragma unroll
    for (int off = 16; off; off >>= 1)
        q += __shfl_xor_sync(0xffffffffu, q, off);

    if (lane == 0) out[row] = -0.5f * q;
}

extern "C" void kernel_launch(void* const* d_in, const int* in_sizes, int n_in,
                              void* d_out, int out_size)
{
    const float* Lf = (const float*)d_in[0];   // [B, 2080]
    const float* mu = (const float*)d_in[1];   // [B, 64]
    const float* a  = (const float*)d_in[2];   // [B, 64]
    float* out = (float*)d_out;                // [B, 1]

    const int B = in_sizes[0] / NB_ELEMS;

    const int threads = 32 * WPB;              // 4 warps = 4 rows per block
    const int blocks  = (B + WPB - 1) / WPB;

    naf_kernel<<<blocks, threads>>>(Lf, mu, a, out, B);
}

// round 11
// speedup vs baseline: 3.5063x; 1.0056x over previous
#include <cuda_runtime.h>
#include <cstdint>

// NAF layer: A = -0.5 * d^T (L L^T) d  ==  -0.5 * ||L^T d||^2
// L lower-triangular, packed row-major (tril order): (i,j) at i*(i+1)/2 + j.
// Diagonal entries exp(x)+eps, off-diagonal raw.
//
// R10: full-row cp.async staging hit 80.7% DRAM / 45.8us. Residual: each warp
// waited for the ENTIRE 8.3KB row before consuming. This version splits the
// staging into 3 cp.async commit groups aligned to triangle row boundaries
// (rows 0..31 | 32..47 | 48..63) and consumes each chunk as it lands
// (wait_group 2 / 1 / 0), overlapping DRAM latency with the triangle walk.
// a/mu loads are issued before any wait. Same smem footprint -> same occupancy.
// One warp per batch row; lane l owns columns j=l and j=l+32.

#define NB_ACTIONS 64
#define NB_ELEMS   2080            // 520 float4 per row
#define EPSV       1e-7f
#define TRI(i) ((i) * ((i) + 1) / 2)
#define WPB    4                   // warps per block

// chunk boundaries in float4 units (floats: 0..527 | 528..1175 | 1176..2079)
#define F4_A   132                 // TRI(32)/4  = 528/4
#define F4_B   294                 // TRI(48)/4  = 1176/4
#define F4_C   520                 // TRI(64)/4  = 2080/4

__global__ __launch_bounds__(32 * WPB, 6)
void naf_kernel(const float* __restrict__ Lf,
                const float* __restrict__ mu,
                const float* __restrict__ a,
                float* __restrict__ out,
                int B)
{
    __shared__ float sbuf[WPB][NB_ELEMS];   // 33,280 B/block

    const int lane   = threadIdx.x & 31;
    const int wlocal = threadIdx.x >> 5;
    const int row    = blockIdx.x * WPB + wlocal;
    if (row >= B) return;

    float* __restrict__ sw = sbuf[wlocal];

    // d-vector loads in flight before anything else
    const size_t vb = (size_t)row * NB_ACTIONS;
    const int j1 = lane + 32;
    const float a0 = a[vb + lane], m0 = mu[vb + lane];
    const float a1 = a[vb + j1],   m1 = mu[vb + j1];

    // ---- Stage row global -> shared in 3 cp.async commit groups ----
    {
        const float4* __restrict__ src =
            (const float4*)(Lf + (size_t)row * NB_ELEMS);
        unsigned int sdst = (unsigned int)__cvta_generic_to_shared(sw);

        // group A: f4 [0, 132)  -> rows 0..31
        #pragma unroll
        for (int it = 0; it < 5; ++it) {
            const int idx = it * 32 + lane;
            if (idx < F4_A)
                asm volatile("cp.async.cg.shared.global [%0], [%1], 16;\n"
                             :: "r"(sdst + idx * 16), "l"(src + idx));
        }
        asm volatile("cp.async.commit_group;\n");

        // group B: f4 [132, 294) -> rows 32..47
        #pragma unroll
        for (int it = 0; it < 6; ++it) {
            const int idx = F4_A + it * 32 + lane;
            if (idx < F4_B)
                asm volatile("cp.async.cg.shared.global [%0], [%1], 16;\n"
                             :: "r"(sdst + idx * 16), "l"(src + idx));
        }
        asm volatile("cp.async.commit_group;\n");

        // group C: f4 [294, 520) -> rows 48..63
        #pragma unroll
        for (int it = 0; it < 8; ++it) {
            const int idx = F4_B + it * 32 + lane;
            if (idx < F4_C)
                asm volatile("cp.async.cg.shared.global [%0], [%1], 16;\n"
                             :: "r"(sdst + idx * 16), "l"(src + idx));
        }
        asm volatile("cp.async.commit_group;\n");
    }

    const float dlo = a0 - m0;   // d[lane]
    const float dhi = a1 - m1;   // d[lane+32]

    float y0 = 0.0f;   // column j = lane
    float y1 = 0.0f;   // column j = lane + 32

    // ---- Chunk A ready: rows 0..31 (y0 only; diag raw, corrected later) ----
    asm volatile("cp.async.wait_group 2;\n" ::: "memory");
    __syncwarp();

    const float diagRaw0 = sw[TRI(lane) + lane];   // in chunk A
    #pragma unroll
    for (int i = 0; i < 32; ++i) {
        const float v  = sw[TRI(i) + lane];        // conflict-free LDS
        const float di = __shfl_sync(0xffffffffu, dlo, i);
        const float m  = (lane <= i) ? di : 0.0f;
        y0 = fmaf(v, m, y0);
    }

    // ---- Chunk B ready: rows 32..47 ----
    asm volatile("cp.async.wait_group 1;\n" ::: "memory");
    __syncwarp();

    #pragma unroll
    for (int i = 32; i < 48; ++i) {
        const int t = TRI(i);
        const float vlo = sw[t + lane];
        const float vhi = sw[t + j1];
        const float di  = __shfl_sync(0xffffffffu, dhi, i - 32);
        y0 = fmaf(vlo, di, y0);
        const float m = (j1 <= i) ? di : 0.0f;
        y1 = fmaf(vhi, m, y1);
    }

    // ---- Chunk C ready: rows 48..63 ----
    asm volatile("cp.async.wait_group 0;\n" ::: "memory");
    __syncwarp();

    #pragma unroll
    for (int i = 48; i < 64; ++i) {
        const int t = TRI(i);
        const float vlo = sw[t + lane];
        const float vhi = sw[t + j1];
        const float di  = __shfl_sync(0xffffffffu, dhi, i - 32);
        y0 = fmaf(vlo, di, y0);
        const float m = (j1 <= i) ? di : 0.0f;
        y1 = fmaf(vhi, m, y1);
    }

    // Diagonal correction: loops added raw*d_self; want (exp(raw)+eps)*d_self.
    const float diagRaw1 = sw[TRI(j1) + j1];
    y0 = fmaf(expf(diagRaw0) + EPSV - diagRaw0, dlo, y0);
    y1 = fmaf(expf(diagRaw1) + EPSV - diagRaw1, dhi, y1);

    // quad = sum_j y_j^2 ; butterfly warp reduction
    float q = fmaf(y0, y0, y1 * y1);
    #pragma unroll
    for (int off = 16; off; off >>= 1)
        q += __shfl_xor_sync(0xffffffffu, q, off);

    if (lane == 0) out[row] = -0.5f * q;
}

extern "C" void kernel_launch(void* const* d_in, const int* in_sizes, int n_in,
                              void* d_out, int out_size)
{
    const float* Lf = (const float*)d_in[0];   // [B, 2080]
    const float* mu = (const float*)d_in[1];   // [B, 64]
    const float* a  = (const float*)d_in[2];   // [B, 64]
    float* out = (float*)d_out;                // [B, 1]

    const int B = in_sizes[0] / NB_ELEMS;

    const int threads = 32 * WPB;              // 4 warps = 4 rows per block
    const int blocks  = (B + WPB - 1) / WPB;

    naf_kernel<<<blocks, threads>>>(Lf, mu, a, out, B);
}